// round 1
// baseline (speedup 1.0000x reference)
#include <cuda_runtime.h>

// Depthwise 3x3 conv, N=16, C=256, H=W=128, pad=1, stride=1, fp32, + bias.
// One block per (n,c) plane. One warp covers a full 128-wide row as 32 float4.
// Column halos via warp shuffle; row reuse via 3-row rolling register window.
// Exactly 1x global read + 1x global write.

namespace {
constexpr int W4 = 32;        // float4 per row (W=128)
constexpr int H = 128;
constexpr int C = 256;
constexpr int ROWS_PER_WARP = 16;   // 8 warps * 16 rows = 128 rows
constexpr int THREADS = 256;

__device__ __forceinline__ void halos(float4 q, int lane, float& lh, float& rh) {
    lh = __shfl_up_sync(0xFFFFFFFFu, q.w, 1);
    rh = __shfl_down_sync(0xFFFFFFFFu, q.x, 1);
    if (lane == 0)  lh = 0.0f;
    if (lane == 31) rh = 0.0f;
}

// Accumulate one input row's 3-tap contribution into a float4 of outputs.
__device__ __forceinline__ void row_contrib(float4& acc, float4 q, float lh, float rh,
                                            float wa, float wb, float wc) {
    acc.x = fmaf(wa, lh,  fmaf(wb, q.x, fmaf(wc, q.y, acc.x)));
    acc.y = fmaf(wa, q.x, fmaf(wb, q.y, fmaf(wc, q.z, acc.y)));
    acc.z = fmaf(wa, q.y, fmaf(wb, q.z, fmaf(wc, q.w, acc.z)));
    acc.w = fmaf(wa, q.z, fmaf(wb, q.w, fmaf(wc, rh,  acc.w)));
}
}  // namespace

__global__ __launch_bounds__(THREADS, 8)
void dwconv3x3_kernel(const float* __restrict__ x,
                      const float* __restrict__ weight,
                      const float* __restrict__ bias,
                      float* __restrict__ out) {
    const int plane = blockIdx.x;            // n*C + c
    const int c = plane & (C - 1);
    const int lane = threadIdx.x & 31;
    const int warp = threadIdx.x >> 5;

    // Per-channel 3x3 weights + bias (uniform across block -> const-cache/broadcast).
    const float* w = weight + c * 9;
    const float w00 = __ldg(w + 0), w01 = __ldg(w + 1), w02 = __ldg(w + 2);
    const float w10 = __ldg(w + 3), w11 = __ldg(w + 4), w12 = __ldg(w + 5);
    const float w20 = __ldg(w + 6), w21 = __ldg(w + 7), w22 = __ldg(w + 8);
    const float b = __ldg(bias + c);

    const size_t base = (size_t)plane * (H * W4);   // in float4 units
    const float4* __restrict__ in4 = reinterpret_cast<const float4*>(x) + base;
    float4* __restrict__ out4 = reinterpret_cast<float4*>(out) + base;

    const int y0 = warp * ROWS_PER_WARP;

    const float4 Z = make_float4(0.f, 0.f, 0.f, 0.f);

    // Rolling 3-row window: m = row y-1, cu = row y, p = row y+1.
    float4 qm, qc;
    float lm, rm, lc, rc;

    qm = (y0 > 0) ? in4[(size_t)(y0 - 1) * W4 + lane] : Z;
    halos(qm, lane, lm, rm);
    qc = in4[(size_t)y0 * W4 + lane];
    halos(qc, lane, lc, rc);

    #pragma unroll 4
    for (int r = 0; r < ROWS_PER_WARP; ++r) {
        const int row = y0 + r;
        float4 qp = (row + 1 < H) ? in4[(size_t)(row + 1) * W4 + lane] : Z;
        float lp, rp;
        halos(qp, lane, lp, rp);

        float4 acc = make_float4(b, b, b, b);
        row_contrib(acc, qm, lm, rm, w00, w01, w02);
        row_contrib(acc, qc, lc, rc, w10, w11, w12);
        row_contrib(acc, qp, lp, rp, w20, w21, w22);

        out4[(size_t)row * W4 + lane] = acc;

        qm = qc; lm = lc; rm = rc;
        qc = qp; lc = lp; rc = rp;
    }
}

extern "C" void kernel_launch(void* const* d_in, const int* in_sizes, int n_in,
                              void* d_out, int out_size) {
    const float* x      = (const float*)d_in[0];
    const float* weight = (const float*)d_in[1];
    const float* bias   = (const float*)d_in[2];
    float* out          = (float*)d_out;

    const int n_planes = 16 * C;   // N * C = 4096 blocks
    dwconv3x3_kernel<<<n_planes, THREADS>>>(x, weight, bias, out);
}

// round 2
// speedup vs baseline: 1.0765x; 1.0765x over previous
#include <cuda_runtime.h>

// Depthwise 3x3 conv, N=16, C=256, H=W=128, pad=1, stride=1, fp32, + bias.
// One block per (n,c) plane; one warp = full 128-wide row as 32 float4.
// R2 change: 4-deep load batching (MLP 1 -> 4) + streaming stores.

namespace {
constexpr int W4 = 32;        // float4 per row (W=128)
constexpr int H = 128;
constexpr int C = 256;
constexpr int ROWS_PER_WARP = 16;   // 8 warps * 16 rows = 128 rows
constexpr int THREADS = 256;
constexpr int UNROLL = 4;

__device__ __forceinline__ void halos(float4 q, int lane, float& lh, float& rh) {
    lh = __shfl_up_sync(0xFFFFFFFFu, q.w, 1);
    rh = __shfl_down_sync(0xFFFFFFFFu, q.x, 1);
    if (lane == 0)  lh = 0.0f;
    if (lane == 31) rh = 0.0f;
}

__device__ __forceinline__ void row_contrib(float4& acc, float4 q, float lh, float rh,
                                            float wa, float wb, float wc) {
    acc.x = fmaf(wa, lh,  fmaf(wb, q.x, fmaf(wc, q.y, acc.x)));
    acc.y = fmaf(wa, q.x, fmaf(wb, q.y, fmaf(wc, q.z, acc.y)));
    acc.z = fmaf(wa, q.y, fmaf(wb, q.z, fmaf(wc, q.w, acc.z)));
    acc.w = fmaf(wa, q.z, fmaf(wb, q.w, fmaf(wc, rh,  acc.w)));
}
}  // namespace

__global__ __launch_bounds__(THREADS, 5)
void dwconv3x3_kernel(const float* __restrict__ x,
                      const float* __restrict__ weight,
                      const float* __restrict__ bias,
                      float* __restrict__ out) {
    const int plane = blockIdx.x;            // n*C + c
    const int c = plane & (C - 1);
    const int lane = threadIdx.x & 31;
    const int warp = threadIdx.x >> 5;

    const float* w = weight + c * 9;
    const float w00 = __ldg(w + 0), w01 = __ldg(w + 1), w02 = __ldg(w + 2);
    const float w10 = __ldg(w + 3), w11 = __ldg(w + 4), w12 = __ldg(w + 5);
    const float w20 = __ldg(w + 6), w21 = __ldg(w + 7), w22 = __ldg(w + 8);
    const float b = __ldg(bias + c);

    const size_t base = (size_t)plane * (H * W4);   // in float4 units
    const float4* __restrict__ in4 = reinterpret_cast<const float4*>(x) + base;
    float4* __restrict__ out4 = reinterpret_cast<float4*>(out) + base;

    const int y0 = warp * ROWS_PER_WARP;
    const float4 Z = make_float4(0.f, 0.f, 0.f, 0.f);

    // Rolling window: qm = row r-1, qc = row r.
    float4 qm, qc;
    float lm, rm, lc, rc;

    qm = (y0 > 0) ? __ldg(&in4[(size_t)(y0 - 1) * W4 + lane]) : Z;
    qc = __ldg(&in4[(size_t)y0 * W4 + lane]);
    halos(qm, lane, lm, rm);
    halos(qc, lane, lc, rc);

    #pragma unroll
    for (int rb = 0; rb < ROWS_PER_WARP / UNROLL; ++rb) {
        const int r0 = y0 + rb * UNROLL;

        // Batch-issue UNROLL independent loads (rows r0+1 .. r0+UNROLL).
        float4 p[UNROLL];
        #pragma unroll
        for (int i = 0; i < UNROLL; ++i) {
            const int row = r0 + 1 + i;
            p[i] = (row < H) ? __ldg(&in4[(size_t)row * W4 + lane]) : Z;
        }

        // Compute + store the UNROLL output rows.
        #pragma unroll
        for (int i = 0; i < UNROLL; ++i) {
            float lp, rp;
            halos(p[i], lane, lp, rp);

            float4 acc = make_float4(b, b, b, b);
            row_contrib(acc, qm, lm, rm, w00, w01, w02);
            row_contrib(acc, qc, lc, rc, w10, w11, w12);
            row_contrib(acc, p[i], lp, rp, w20, w21, w22);

            __stcs(&out4[(size_t)(r0 + i) * W4 + lane], acc);

            qm = qc; lm = lc; rm = rc;
            qc = p[i]; lc = lp; rc = rp;
        }
    }
}

extern "C" void kernel_launch(void* const* d_in, const int* in_sizes, int n_in,
                              void* d_out, int out_size) {
    const float* x      = (const float*)d_in[0];
    const float* weight = (const float*)d_in[1];
    const float* bias   = (const float*)d_in[2];
    float* out          = (float*)d_out;

    const int n_planes = 16 * C;   // N * C = 4096 blocks
    dwconv3x3_kernel<<<n_planes, THREADS>>>(x, weight, bias, out);
}

// round 3
// speedup vs baseline: 1.0773x; 1.0008x over previous
#include <cuda_runtime.h>

// Depthwise 3x3 conv, N=16, C=256, H=W=128, pad=1, stride=1, fp32, + bias.
// One warp = full 128-wide row as 32 float4; 16 rows per warp.
// R3 change: 128-thread blocks (4 warps, 64 rows, 2 blocks/plane) -> finer
// scheduling granularity (halved drain tail) + higher occupancy cap (10
// resident blocks/SM = 40 warps vs 34 before). Load batching (MLP=4) and
// streaming stores kept from R2.

namespace {
constexpr int W4 = 32;        // float4 per row (W=128)
constexpr int H = 128;
constexpr int C = 256;
constexpr int ROWS_PER_WARP = 16;
constexpr int WARPS = 4;                       // block covers 64 rows
constexpr int THREADS = WARPS * 32;            // 128
constexpr int BLOCKS_PER_PLANE = H / (WARPS * ROWS_PER_WARP);  // 2
constexpr int UNROLL = 4;

__device__ __forceinline__ void halos(float4 q, int lane, float& lh, float& rh) {
    lh = __shfl_up_sync(0xFFFFFFFFu, q.w, 1);
    rh = __shfl_down_sync(0xFFFFFFFFu, q.x, 1);
    if (lane == 0)  lh = 0.0f;
    if (lane == 31) rh = 0.0f;
}

__device__ __forceinline__ void row_contrib(float4& acc, float4 q, float lh, float rh,
                                            float wa, float wb, float wc) {
    acc.x = fmaf(wa, lh,  fmaf(wb, q.x, fmaf(wc, q.y, acc.x)));
    acc.y = fmaf(wa, q.x, fmaf(wb, q.y, fmaf(wc, q.z, acc.y)));
    acc.z = fmaf(wa, q.y, fmaf(wb, q.z, fmaf(wc, q.w, acc.z)));
    acc.w = fmaf(wa, q.z, fmaf(wb, q.w, fmaf(wc, rh,  acc.w)));
}
}  // namespace

__global__ __launch_bounds__(THREADS, 10)
void dwconv3x3_kernel(const float* __restrict__ x,
                      const float* __restrict__ weight,
                      const float* __restrict__ bias,
                      float* __restrict__ out) {
    const int blk   = blockIdx.x;
    const int plane = blk / BLOCKS_PER_PLANE;      // n*C + c
    const int half  = blk - plane * BLOCKS_PER_PLANE;
    const int c = plane & (C - 1);
    const int lane = threadIdx.x & 31;
    const int warp = threadIdx.x >> 5;

    const float* w = weight + c * 9;
    const float w00 = __ldg(w + 0), w01 = __ldg(w + 1), w02 = __ldg(w + 2);
    const float w10 = __ldg(w + 3), w11 = __ldg(w + 4), w12 = __ldg(w + 5);
    const float w20 = __ldg(w + 6), w21 = __ldg(w + 7), w22 = __ldg(w + 8);
    const float b = __ldg(bias + c);

    const size_t base = (size_t)plane * (H * W4);   // in float4 units
    const float4* __restrict__ in4 = reinterpret_cast<const float4*>(x) + base;
    float4* __restrict__ out4 = reinterpret_cast<float4*>(out) + base;

    const int y0 = (half * WARPS + warp) * ROWS_PER_WARP;
    const float4 Z = make_float4(0.f, 0.f, 0.f, 0.f);

    // Rolling window: qm = row r-1, qc = row r.
    float4 qm, qc;
    float lm, rm, lc, rc;

    qm = (y0 > 0) ? __ldg(&in4[(size_t)(y0 - 1) * W4 + lane]) : Z;
    qc = __ldg(&in4[(size_t)y0 * W4 + lane]);
    halos(qm, lane, lm, rm);
    halos(qc, lane, lc, rc);

    #pragma unroll
    for (int rb = 0; rb < ROWS_PER_WARP / UNROLL; ++rb) {
        const int r0 = y0 + rb * UNROLL;

        // Batch-issue UNROLL independent loads (rows r0+1 .. r0+UNROLL).
        float4 p[UNROLL];
        #pragma unroll
        for (int i = 0; i < UNROLL; ++i) {
            const int row = r0 + 1 + i;
            p[i] = (row < H) ? __ldg(&in4[(size_t)row * W4 + lane]) : Z;
        }

        // Compute + store the UNROLL output rows.
        #pragma unroll
        for (int i = 0; i < UNROLL; ++i) {
            float lp, rp;
            halos(p[i], lane, lp, rp);

            float4 acc = make_float4(b, b, b, b);
            row_contrib(acc, qm, lm, rm, w00, w01, w02);
            row_contrib(acc, qc, lc, rc, w10, w11, w12);
            row_contrib(acc, p[i], lp, rp, w20, w21, w22);

            __stcs(&out4[(size_t)(r0 + i) * W4 + lane], acc);

            qm = qc; lm = lc; rm = rc;
            qc = p[i]; lc = lp; rc = rp;
        }
    }
}

extern "C" void kernel_launch(void* const* d_in, const int* in_sizes, int n_in,
                              void* d_out, int out_size) {
    const float* x      = (const float*)d_in[0];
    const float* weight = (const float*)d_in[1];
    const float* bias   = (const float*)d_in[2];
    float* out          = (float*)d_out;

    const int n_blocks = 16 * C * BLOCKS_PER_PLANE;   // 8192
    dwconv3x3_kernel<<<n_blocks, THREADS>>>(x, weight, bias, out);
}